// round 2
// baseline (speedup 1.0000x reference)
#include <cuda_runtime.h>
#include <cstdint>

#define BATCH 2
#define SEQ   2048
#define DIM   1024
#define NST   16
#define DTR   64
#define XD    96   /* dt_rank + 2*N */

#define MROWS (BATCH*SEQ) /* 4096 */

// ---------------- scratch (allocation-free: __device__ globals) ----------------
__device__ float g_xz[(size_t)MROWS * 2 * DIM];   // 33.5 MB
__device__ float g_xc[(size_t)MROWS * DIM];       // 16.8 MB
__device__ float g_xdbl[(size_t)MROWS * XD];      // 1.6 MB
__device__ float g_delta[(size_t)MROWS * DIM];    // 16.8 MB
__device__ float g_yg[(size_t)MROWS * DIM];       // 16.8 MB

// ---------------- helpers ----------------
__device__ __forceinline__ float softplusf(float x) {
    return (x > 20.f) ? x : log1pf(__expf(x));
}

// ---------------- generic NT SGEMM: C = A(MxK) * B(NxK)^T ----------------
// A row-major lda, B row-major ldb (K contiguous in both), C row-major ldc.
// ACT: 0 = none, 1 = softplus(c + bias[n])
// Assumes M % BM == 0 and K % BK == 0 (true for all our shapes); guards N only.
template<int BM, int BN, int BK, int TM, int TN, int ACT>
__global__ void __launch_bounds__((BM/TM)*(BN/TN))
sgemm_nt(const float* __restrict__ A, int lda,
         const float* __restrict__ Bm, int ldb,
         float* __restrict__ C, int ldc,
         const float* __restrict__ bias,
         int M, int N, int K)
{
    constexpr int THREADS = (BM/TM)*(BN/TN);
    constexpr int A_SLOTS = BM*BK/4;   // float4 slots
    constexpr int B_SLOTS = BN*BK/4;
    static_assert(A_SLOTS % THREADS == 0, "");
    static_assert(B_SLOTS % THREADS == 0, "");

    __shared__ float As[BK][BM];
    __shared__ float Bs[BK][BN];

    const int tid = threadIdx.x;
    const int tx = tid % (BN/TN);
    const int ty = tid / (BN/TN);
    const int m0 = blockIdx.y * BM;
    const int n0 = blockIdx.x * BN;

    float acc[TM][TN];
#pragma unroll
    for (int i = 0; i < TM; i++)
#pragma unroll
        for (int j = 0; j < TN; j++) acc[i][j] = 0.f;

    for (int k0 = 0; k0 < K; k0 += BK) {
        // load A tile (transposed into SMEM)
#pragma unroll
        for (int it = 0; it < A_SLOTS/THREADS; it++) {
            int s = tid + it*THREADS;
            int row = s / (BK/4);
            int kk  = (s % (BK/4)) * 4;
            float4 v = *reinterpret_cast<const float4*>(
                A + (size_t)(m0 + row) * lda + k0 + kk);
            As[kk+0][row] = v.x; As[kk+1][row] = v.y;
            As[kk+2][row] = v.z; As[kk+3][row] = v.w;
        }
        // load B tile (transposed into SMEM), guard N
#pragma unroll
        for (int it = 0; it < B_SLOTS/THREADS; it++) {
            int s = tid + it*THREADS;
            int row = s / (BK/4);
            int kk  = (s % (BK/4)) * 4;
            float4 v = make_float4(0.f, 0.f, 0.f, 0.f);
            if (n0 + row < N)
                v = *reinterpret_cast<const float4*>(
                    Bm + (size_t)(n0 + row) * ldb + k0 + kk);
            Bs[kk+0][row] = v.x; Bs[kk+1][row] = v.y;
            Bs[kk+2][row] = v.z; Bs[kk+3][row] = v.w;
        }
        __syncthreads();

#pragma unroll
        for (int kk = 0; kk < BK; kk++) {
            float a[TM], b[TN];
#pragma unroll
            for (int i = 0; i < TM; i += 4) {
                float4 v = *reinterpret_cast<const float4*>(&As[kk][ty*TM + i]);
                a[i+0] = v.x; a[i+1] = v.y; a[i+2] = v.z; a[i+3] = v.w;
            }
#pragma unroll
            for (int j = 0; j < TN; j += 4) {
                float4 v = *reinterpret_cast<const float4*>(&Bs[kk][tx*TN + j]);
                b[j+0] = v.x; b[j+1] = v.y; b[j+2] = v.z; b[j+3] = v.w;
            }
#pragma unroll
            for (int i = 0; i < TM; i++)
#pragma unroll
                for (int j = 0; j < TN; j++)
                    acc[i][j] = fmaf(a[i], b[j], acc[i][j]);
        }
        __syncthreads();
    }

    // epilogue
#pragma unroll
    for (int i = 0; i < TM; i++) {
        int m = m0 + ty*TM + i;
#pragma unroll
        for (int j = 0; j < TN; j++) {
            int n = n0 + tx*TN + j;
            if (n < N) {
                float v = acc[i][j];
                if (ACT == 1) v = softplusf(v + bias[n]);
                C[(size_t)m * ldc + n] = v;
            }
        }
    }
}

// ---------------- depthwise conv1d k=3 pad=1 (input = first half of xz) --------
__global__ void conv_kernel(const float* __restrict__ xz,
                            const float* __restrict__ w,
                            const float* __restrict__ bconv,
                            float* __restrict__ xc)
{
    int idx = blockIdx.x * blockDim.x + threadIdx.x;   // over MROWS*DIM
    if (idx >= MROWS * DIM) return;
    int d = idx & (DIM - 1);
    int l = (idx >> 10) & (SEQ - 1);
    const float* base = xz + (size_t)(idx >> 10) * (2*DIM) + d;
    float w0 = w[d*3+0], w1 = w[d*3+1], w2 = w[d*3+2];
    float acc = bconv[d];
    if (l > 0)       acc = fmaf(w0, base[-(2*DIM)], acc);
    acc = fmaf(w1, base[0], acc);
    if (l < SEQ - 1) acc = fmaf(w2, base[2*DIM], acc);
    xc[idx] = acc;
}

// ---------------- selective scan + D skip + SiLU(z) gate -----------------------
// One warp = 2 channels x 16 states. Lanes 0-15: chan0 state n; 16-31: chan1.
__global__ void scan_kernel(const float* __restrict__ delta,
                            const float* __restrict__ u,
                            const float* __restrict__ xdbl,
                            const float* __restrict__ xz,
                            const float* __restrict__ A_log,
                            const float* __restrict__ Dp,
                            float* __restrict__ yg)
{
    const int lane = threadIdx.x & 31;
    const int warp = threadIdx.x >> 5;
    const int n = lane & 15;
    const int chan = blockIdx.x * ((int)blockDim.x >> 4) + (warp << 1) + (lane >> 4);
    const int b = chan >> 10;          // chan / DIM
    const int d = chan & (DIM - 1);

    const float A    = -__expf(__ldg(A_log + d*NST + n));
    const float Dpar = __ldg(Dp + d);

    const size_t row0 = (size_t)b * SEQ;
    const float* pD  = delta + row0 * DIM + d;
    const float* pU  = u     + row0 * DIM + d;
    const float* pBC = xdbl  + row0 * XD;
    const float* pZ  = xz    + row0 * (2*DIM) + DIM + d;
    float*       pY  = yg    + row0 * DIM + d;

    float s = 0.f;
#pragma unroll 2
    for (int t = 0; t < SEQ; ++t) {
        float dt = __ldg(pD);
        float uu = __ldg(pU);
        float Bn = __ldg(pBC + DTR + n);
        float Cn = __ldg(pBC + DTR + NST + n);

        float dA = __expf(dt * A);
        s = fmaf(dA, s, dt * Bn * uu);

        float p = s * Cn;
        p += __shfl_xor_sync(0xffffffffu, p, 1);
        p += __shfl_xor_sync(0xffffffffu, p, 2);
        p += __shfl_xor_sync(0xffffffffu, p, 4);
        p += __shfl_xor_sync(0xffffffffu, p, 8);

        if (n == 0) {
            float z = __ldg(pZ);
            float sig = __fdividef(1.f, 1.f + __expf(-z));
            pY[0] = fmaf(uu, Dpar, p) * (z * sig);
        }
        pD += DIM; pU += DIM; pBC += XD; pZ += 2*DIM; pY += DIM;
    }
}

// ---------------- launcher ----------------
extern "C" void kernel_launch(void* const* d_in, const int* in_sizes, int n_in,
                              void* d_out, int out_size)
{
    const float* x          = (const float*)d_in[0];
    const float* in_proj_w  = (const float*)d_in[1];
    const float* conv_w     = (const float*)d_in[2];
    const float* conv_b     = (const float*)d_in[3];
    const float* A_log      = (const float*)d_in[4];
    const float* D_param    = (const float*)d_in[5];
    const float* x_proj_w   = (const float*)d_in[6];
    const float* dt_proj_w  = (const float*)d_in[7];
    const float* dt_proj_b  = (const float*)d_in[8];
    const float* out_proj_w = (const float*)d_in[9];
    float* out = (float*)d_out;

    float *xz, *xc, *xdbl, *delta, *yg;
    cudaGetSymbolAddress((void**)&xz,    g_xz);
    cudaGetSymbolAddress((void**)&xc,    g_xc);
    cudaGetSymbolAddress((void**)&xdbl,  g_xdbl);
    cudaGetSymbolAddress((void**)&delta, g_delta);
    cudaGetSymbolAddress((void**)&yg,    g_yg);

    const int M = MROWS;

    // 1. in_proj: xz = x @ in_proj_w^T   (4096 x 2048 x 1024)
    sgemm_nt<128,128,16,8,8,0><<<dim3((2*DIM)/128, M/128), 256>>>(
        x, DIM, in_proj_w, DIM, xz, 2*DIM, nullptr, M, 2*DIM, DIM);

    // 2. depthwise conv1d on first half of xz -> xc
    conv_kernel<<<(M*DIM)/256, 256>>>(xz, conv_w, conv_b, xc);

    // 3. x_proj: xdbl = xc @ x_proj_w^T  (4096 x 96 x 1024)
    sgemm_nt<64,64,16,4,4,0><<<dim3((XD + 63)/64, M/64), 256>>>(
        xc, DIM, x_proj_w, DIM, xdbl, XD, nullptr, M, XD, DIM);

    // 4. dt_proj + softplus: delta = softplus(xdbl[:, :64] @ dt_proj_w^T + b)
    sgemm_nt<128,128,16,8,8,1><<<dim3(DIM/128, M/128), 256>>>(
        xdbl, XD, dt_proj_w, DTR, delta, DIM, dt_proj_b, M, DIM, DTR);

    // 5. selective scan + D skip + SiLU(z) gate -> yg
    scan_kernel<<<(BATCH*DIM)/8, 128>>>(delta, xc, xdbl, xz, A_log, D_param, yg);

    // 6. out_proj: out = yg @ out_proj_w^T  (4096 x 1024 x 1024)
    sgemm_nt<128,128,16,8,8,0><<<dim3(DIM/128, M/128), 256>>>(
        yg, DIM, out_proj_w, DIM, out, DIM, nullptr, M, DIM, DIM);
}

// round 3
// speedup vs baseline: 1.3940x; 1.3940x over previous
#include <cuda_runtime.h>
#include <cstdint>

#define BATCH 2
#define SEQ   2048
#define DIM   1024
#define NST   16
#define DTR   64
#define XD    96   /* dt_rank + 2*N */

#define MROWS (BATCH*SEQ) /* 4096 */

// ---------------- scratch (allocation-free: __device__ globals) ----------------
__device__ float g_xz[(size_t)MROWS * 2 * DIM];   // 33.5 MB
__device__ float g_xc[(size_t)MROWS * DIM];       // 16.8 MB
__device__ float g_xdbl[(size_t)MROWS * XD];      // 1.6 MB
__device__ float g_delta[(size_t)MROWS * DIM];    // 16.8 MB
__device__ float g_yg[(size_t)MROWS * DIM];       // 16.8 MB

// ---------------- helpers ----------------
__device__ __forceinline__ float softplusf(float x) {
    return (x > 20.f) ? x : log1pf(__expf(x));
}

__device__ __forceinline__ uint32_t f2tf32(float x) {
    uint32_t r;
    asm("cvt.rna.tf32.f32 %0, %1;" : "=r"(r) : "f"(x));
    return r;
}

// =====================================================================
// TF32 tensor-core NT GEMM: C = A(MxK) * B(NxK)^T, fp32 accumulate.
// BK = 32, warp tile WM x WN, m16n8k8 mma fragments.
// ACT: 0 = none, 1 = softplus(c + bias[n])
// Requires: M % BM == 0, K % 32 == 0. N guarded.
// =====================================================================
template<int BM, int BN, int WM, int WN, int ACT>
__global__ void __launch_bounds__((BM/WM)*(BN/WN)*32)
gemm_tf32(const float* __restrict__ A, int lda,
          const float* __restrict__ Bm, int ldb,
          float* __restrict__ C, int ldc,
          const float* __restrict__ bias,
          int M, int N, int K)
{
    constexpr int BK = 32;
    constexpr int PITCH = BK + 4;            // 36 floats -> conflict-free frag loads
    constexpr int WARPS_N = BN / WN;
    constexpr int THREADS = (BM/WM) * (BN/WN) * 32;
    constexpr int MT = WM / 16;
    constexpr int NT = WN / 8;
    constexpr int A_IT = (BM*BK/4) / THREADS;   // float4 loads per thread
    constexpr int B_IT = (BN*BK/4) / THREADS;
    static_assert((BM*BK/4) % THREADS == 0, "");
    static_assert((BN*BK/4) % THREADS == 0, "");

    __shared__ uint32_t As[BM * PITCH];
    __shared__ uint32_t Bs[BN * PITCH];

    const int tid  = threadIdx.x;
    const int wid  = tid >> 5;
    const int lane = tid & 31;
    const int g    = lane >> 2;   // 0..7
    const int tig  = lane & 3;    // 0..3
    const int wm   = (wid / WARPS_N) * WM;
    const int wn   = (wid % WARPS_N) * WN;
    const int m0   = blockIdx.y * BM;
    const int n0   = blockIdx.x * BN;

    float c[MT][NT][4];
#pragma unroll
    for (int i = 0; i < MT; i++)
#pragma unroll
        for (int j = 0; j < NT; j++)
#pragma unroll
            for (int r = 0; r < 4; r++) c[i][j][r] = 0.f;

    for (int k0 = 0; k0 < K; k0 += BK) {
        // ---- global -> smem (convert to tf32 once) ----
#pragma unroll
        for (int it = 0; it < A_IT; it++) {
            int s   = tid + it*THREADS;
            int row = s >> 3;            // / (BK/4)
            int kq  = (s & 7) * 4;
            float4 v = *reinterpret_cast<const float4*>(
                A + (size_t)(m0 + row) * lda + k0 + kq);
            uint32_t* dst = &As[row * PITCH + kq];
            dst[0] = f2tf32(v.x); dst[1] = f2tf32(v.y);
            dst[2] = f2tf32(v.z); dst[3] = f2tf32(v.w);
        }
#pragma unroll
        for (int it = 0; it < B_IT; it++) {
            int s   = tid + it*THREADS;
            int row = s >> 3;
            int kq  = (s & 7) * 4;
            float4 v = make_float4(0.f,0.f,0.f,0.f);
            if (n0 + row < N)
                v = *reinterpret_cast<const float4*>(
                    Bm + (size_t)(n0 + row) * ldb + k0 + kq);
            uint32_t* dst = &Bs[row * PITCH + kq];
            dst[0] = f2tf32(v.x); dst[1] = f2tf32(v.y);
            dst[2] = f2tf32(v.z); dst[3] = f2tf32(v.w);
        }
        __syncthreads();

        // ---- mma over 4 k-steps of 8 ----
#pragma unroll
        for (int kk = 0; kk < BK; kk += 8) {
            uint32_t a[MT][4], b[NT][2];
#pragma unroll
            for (int mt = 0; mt < MT; mt++) {
                int base = (wm + mt*16 + g) * PITCH + kk + tig;
                a[mt][0] = As[base];
                a[mt][1] = As[base + 8*PITCH];
                a[mt][2] = As[base + 4];
                a[mt][3] = As[base + 8*PITCH + 4];
            }
#pragma unroll
            for (int nt = 0; nt < NT; nt++) {
                int base = (wn + nt*8 + g) * PITCH + kk + tig;
                b[nt][0] = Bs[base];
                b[nt][1] = Bs[base + 4];
            }
#pragma unroll
            for (int mt = 0; mt < MT; mt++)
#pragma unroll
                for (int nt = 0; nt < NT; nt++) {
                    asm volatile(
                        "mma.sync.aligned.m16n8k8.row.col.f32.tf32.tf32.f32 "
                        "{%0,%1,%2,%3}, {%4,%5,%6,%7}, {%8,%9}, {%0,%1,%2,%3};\n"
                        : "+f"(c[mt][nt][0]), "+f"(c[mt][nt][1]),
                          "+f"(c[mt][nt][2]), "+f"(c[mt][nt][3])
                        : "r"(a[mt][0]), "r"(a[mt][1]), "r"(a[mt][2]), "r"(a[mt][3]),
                          "r"(b[nt][0]), "r"(b[nt][1]));
                }
        }
        __syncthreads();
    }

    // ---- epilogue ----
#pragma unroll
    for (int mt = 0; mt < MT; mt++) {
        int r0 = m0 + wm + mt*16 + g;
#pragma unroll
        for (int nt = 0; nt < NT; nt++) {
            int n = n0 + wn + nt*8 + tig*2;
            if (n < N) {
                float v0 = c[mt][nt][0], v1 = c[mt][nt][1];
                float v2 = c[mt][nt][2], v3 = c[mt][nt][3];
                if (ACT == 1) {
                    v0 = softplusf(v0 + bias[n]);   v1 = softplusf(v1 + bias[n+1]);
                    v2 = softplusf(v2 + bias[n]);   v3 = softplusf(v3 + bias[n+1]);
                }
                *reinterpret_cast<float2*>(C + (size_t)r0 * ldc + n)     = make_float2(v0, v1);
                *reinterpret_cast<float2*>(C + (size_t)(r0+8) * ldc + n) = make_float2(v2, v3);
            }
        }
    }
}

// ---------------- FFMA NT SGEMM (kept for x_proj, exact fp32) ----------------
template<int BM, int BN, int BK, int TM, int TN>
__global__ void __launch_bounds__((BM/TM)*(BN/TN))
sgemm_nt(const float* __restrict__ A, int lda,
         const float* __restrict__ Bm, int ldb,
         float* __restrict__ C, int ldc,
         int M, int N, int K)
{
    constexpr int THREADS = (BM/TM)*(BN/TN);
    constexpr int A_SLOTS = BM*BK/4;
    constexpr int B_SLOTS = BN*BK/4;

    __shared__ float As[BK][BM];
    __shared__ float Bs[BK][BN];

    const int tid = threadIdx.x;
    const int tx = tid % (BN/TN);
    const int ty = tid / (BN/TN);
    const int m0 = blockIdx.y * BM;
    const int n0 = blockIdx.x * BN;

    float acc[TM][TN];
#pragma unroll
    for (int i = 0; i < TM; i++)
#pragma unroll
        for (int j = 0; j < TN; j++) acc[i][j] = 0.f;

    for (int k0 = 0; k0 < K; k0 += BK) {
#pragma unroll
        for (int it = 0; it < A_SLOTS/THREADS; it++) {
            int s = tid + it*THREADS;
            int row = s / (BK/4);
            int kk  = (s % (BK/4)) * 4;
            float4 v = *reinterpret_cast<const float4*>(
                A + (size_t)(m0 + row) * lda + k0 + kk);
            As[kk+0][row] = v.x; As[kk+1][row] = v.y;
            As[kk+2][row] = v.z; As[kk+3][row] = v.w;
        }
#pragma unroll
        for (int it = 0; it < B_SLOTS/THREADS; it++) {
            int s = tid + it*THREADS;
            int row = s / (BK/4);
            int kk  = (s % (BK/4)) * 4;
            float4 v = make_float4(0.f, 0.f, 0.f, 0.f);
            if (n0 + row < N)
                v = *reinterpret_cast<const float4*>(
                    Bm + (size_t)(n0 + row) * ldb + k0 + kk);
            Bs[kk+0][row] = v.x; Bs[kk+1][row] = v.y;
            Bs[kk+2][row] = v.z; Bs[kk+3][row] = v.w;
        }
        __syncthreads();

#pragma unroll
        for (int kk = 0; kk < BK; kk++) {
            float a[TM], b[TN];
#pragma unroll
            for (int i = 0; i < TM; i += 4) {
                float4 v = *reinterpret_cast<const float4*>(&As[kk][ty*TM + i]);
                a[i+0] = v.x; a[i+1] = v.y; a[i+2] = v.z; a[i+3] = v.w;
            }
#pragma unroll
            for (int j = 0; j < TN; j += 4) {
                float4 v = *reinterpret_cast<const float4*>(&Bs[kk][tx*TN + j]);
                b[j+0] = v.x; b[j+1] = v.y; b[j+2] = v.z; b[j+3] = v.w;
            }
#pragma unroll
            for (int i = 0; i < TM; i++)
#pragma unroll
                for (int j = 0; j < TN; j++)
                    acc[i][j] = fmaf(a[i], b[j], acc[i][j]);
        }
        __syncthreads();
    }

#pragma unroll
    for (int i = 0; i < TM; i++) {
        int m = m0 + ty*TM + i;
#pragma unroll
        for (int j = 0; j < TN; j++) {
            int n = n0 + tx*TN + j;
            if (n < N) C[(size_t)m * ldc + n] = acc[i][j];
        }
    }
}

// ---------------- depthwise conv1d k=3 pad=1 (input = first half of xz) --------
__global__ void conv_kernel(const float* __restrict__ xz,
                            const float* __restrict__ w,
                            const float* __restrict__ bconv,
                            float* __restrict__ xc)
{
    int idx = blockIdx.x * blockDim.x + threadIdx.x;   // over MROWS*DIM
    if (idx >= MROWS * DIM) return;
    int d = idx & (DIM - 1);
    int l = (idx >> 10) & (SEQ - 1);
    const float* base = xz + (size_t)(idx >> 10) * (2*DIM) + d;
    float w0 = w[d*3+0], w1 = w[d*3+1], w2 = w[d*3+2];
    float acc = bconv[d];
    if (l > 0)       acc = fmaf(w0, base[-(2*DIM)], acc);
    acc = fmaf(w1, base[0], acc);
    if (l < SEQ - 1) acc = fmaf(w2, base[2*DIM], acc);
    xc[idx] = acc;
}

// ---------------- selective scan + D skip + SiLU(z) gate -----------------------
// One warp = 2 channels x 16 states. Lanes 0-15: chan0 state n; 16-31: chan1.
__global__ void scan_kernel(const float* __restrict__ delta,
                            const float* __restrict__ u,
                            const float* __restrict__ xdbl,
                            const float* __restrict__ xz,
                            const float* __restrict__ A_log,
                            const float* __restrict__ Dp,
                            float* __restrict__ yg)
{
    const int lane = threadIdx.x & 31;
    const int warp = threadIdx.x >> 5;
    const int n = lane & 15;
    const int chan = blockIdx.x * ((int)blockDim.x >> 4) + (warp << 1) + (lane >> 4);
    const int b = chan >> 10;          // chan / DIM
    const int d = chan & (DIM - 1);

    const float A    = -__expf(__ldg(A_log + d*NST + n));
    const float Dpar = __ldg(Dp + d);

    const size_t row0 = (size_t)b * SEQ;
    const float* pD  = delta + row0 * DIM + d;
    const float* pU  = u     + row0 * DIM + d;
    const float* pBC = xdbl  + row0 * XD;
    const float* pZ  = xz    + row0 * (2*DIM) + DIM + d;
    float*       pY  = yg    + row0 * DIM + d;

    float s = 0.f;
#pragma unroll 2
    for (int t = 0; t < SEQ; ++t) {
        float dt = __ldg(pD);
        float uu = __ldg(pU);
        float Bn = __ldg(pBC + DTR + n);
        float Cn = __ldg(pBC + DTR + NST + n);

        float dA = __expf(dt * A);
        s = fmaf(dA, s, dt * Bn * uu);

        float p = s * Cn;
        p += __shfl_xor_sync(0xffffffffu, p, 1);
        p += __shfl_xor_sync(0xffffffffu, p, 2);
        p += __shfl_xor_sync(0xffffffffu, p, 4);
        p += __shfl_xor_sync(0xffffffffu, p, 8);

        if (n == 0) {
            float z = __ldg(pZ);
            float sig = __fdividef(1.f, 1.f + __expf(-z));
            pY[0] = fmaf(uu, Dpar, p) * (z * sig);
        }
        pD += DIM; pU += DIM; pBC += XD; pZ += 2*DIM; pY += DIM;
    }
}

// ---------------- launcher ----------------
extern "C" void kernel_launch(void* const* d_in, const int* in_sizes, int n_in,
                              void* d_out, int out_size)
{
    const float* x          = (const float*)d_in[0];
    const float* in_proj_w  = (const float*)d_in[1];
    const float* conv_w     = (const float*)d_in[2];
    const float* conv_b     = (const float*)d_in[3];
    const float* A_log      = (const float*)d_in[4];
    const float* D_param    = (const float*)d_in[5];
    const float* x_proj_w   = (const float*)d_in[6];
    const float* dt_proj_w  = (const float*)d_in[7];
    const float* dt_proj_b  = (const float*)d_in[8];
    const float* out_proj_w = (const float*)d_in[9];
    float* out = (float*)d_out;

    float *xz, *xc, *xdbl, *delta, *yg;
    cudaGetSymbolAddress((void**)&xz,    g_xz);
    cudaGetSymbolAddress((void**)&xc,    g_xc);
    cudaGetSymbolAddress((void**)&xdbl,  g_xdbl);
    cudaGetSymbolAddress((void**)&delta, g_delta);
    cudaGetSymbolAddress((void**)&yg,    g_yg);

    const int M = MROWS;

    // 1. in_proj: xz = x @ in_proj_w^T   (4096 x 2048 x 1024)  [tf32 tensor core]
    gemm_tf32<128,128,64,32,0><<<dim3((2*DIM)/128, M/128), 256>>>(
        x, DIM, in_proj_w, DIM, xz, 2*DIM, nullptr, M, 2*DIM, DIM);

    // 2. depthwise conv1d on first half of xz -> xc
    conv_kernel<<<(M*DIM)/256, 256>>>(xz, conv_w, conv_b, xc);

    // 3. x_proj: xdbl = xc @ x_proj_w^T  (4096 x 96 x 1024)  [exact fp32]
    sgemm_nt<64,64,16,4,4><<<dim3((XD + 63)/64, M/64), 256>>>(
        xc, DIM, x_proj_w, DIM, xdbl, XD, M, XD, DIM);

    // 4. dt_proj + softplus: delta = softplus(xdbl[:, :64] @ dt_proj_w^T + b) [tf32]
    gemm_tf32<128,128,64,32,1><<<dim3(DIM/128, M/128), 256>>>(
        xdbl, XD, dt_proj_w, DTR, delta, DIM, dt_proj_b, M, DIM, DTR);

    // 5. selective scan + D skip + SiLU(z) gate -> yg
    scan_kernel<<<(BATCH*DIM)/8, 128>>>(delta, xc, xdbl, xz, A_log, D_param, yg);

    // 6. out_proj: out = yg @ out_proj_w^T  (4096 x 1024 x 1024)  [tf32]
    gemm_tf32<128,128,64,32,0><<<dim3(DIM/128, M/128), 256>>>(
        yg, DIM, out_proj_w, DIM, out, DIM, nullptr, M, DIM, DIM);
}